// round 14
// baseline (speedup 1.0000x reference)
#include <cuda_runtime.h>
#include <stdint.h>

#define B_     4
#define CDIM   512
#define LSEQ   2048
#define HEADS_ 8
#define DHEAD  64
#define HID    512
#define O3     1536
#define QSCALE 0.125f
#define LOG2E  1.44269504088896f

typedef uint32_t u32;

// ------------------------- scratch (device globals) -------------------------
__device__ float    g_att[(size_t)B_ * HID * LSEQ];   // [b][h*64+d][l]
__device__ uint16_t g_w16[O3 * CDIM];                 // w_qkv fp16 (q rows pre-scaled)
__device__ uint16_t g_x16[(size_t)B_ * CDIM * LSEQ];  // x fp16
__device__ uint16_t g_qh[(size_t)B_ * HEADS_ * LSEQ * DHEAD]; // [b][h][l][d] fp16
__device__ uint16_t g_kh[(size_t)B_ * HEADS_ * LSEQ * DHEAD]; // fp16
__device__ uint16_t g_vh[(size_t)B_ * HEADS_ * DHEAD * LSEQ]; // [b][h][d][l] fp16

// ------------------------------- helpers -------------------------------------
__device__ __forceinline__ u32 smem_u32(const void* p) {
    u32 a; asm("{ .reg .u64 t; cvta.to.shared.u64 t, %1; cvt.u32.u64 %0, t; }"
               : "=r"(a) : "l"(p));
    return a;
}
__device__ __forceinline__ u32 pack_bf16x2(float a, float b) {   // lo=a, hi=b
    u32 r; asm("cvt.rn.bf16x2.f32 %0, %1, %2;" : "=r"(r) : "f"(b), "f"(a));
    return r;
}
__device__ __forceinline__ u32 pack_f16x2(float a, float b) {    // lo=a, hi=b
    u32 r; asm("cvt.rn.f16x2.f32 %0, %1, %2;" : "=r"(r) : "f"(b), "f"(a));
    return r;
}
__device__ __forceinline__ float ex2f(float x) {
    float y; asm("ex2.approx.f32 %0, %1;" : "=f"(y) : "f"(x)); return y;
}
__device__ __forceinline__ float bf_lo(u32 w) { return __uint_as_float(w << 16); }
__device__ __forceinline__ float bf_hi(u32 w) { return __uint_as_float(w & 0xffff0000u); }
__device__ __forceinline__ void split_pair(float a, float b, u32& hw, u32& lw) {
    hw = pack_bf16x2(a, b);
    lw = pack_bf16x2(a - bf_lo(hw), b - bf_hi(hw));
}
__device__ __forceinline__ void mma_bf(float c[4], const u32 a[4], u32 b0, u32 b1) {
    asm volatile(
        "mma.sync.aligned.m16n8k16.row.col.f32.bf16.bf16.f32 "
        "{%0,%1,%2,%3}, {%4,%5,%6,%7}, {%8,%9}, {%0,%1,%2,%3};"
        : "+f"(c[0]), "+f"(c[1]), "+f"(c[2]), "+f"(c[3])
        : "r"(a[0]), "r"(a[1]), "r"(a[2]), "r"(a[3]), "r"(b0), "r"(b1));
}
__device__ __forceinline__ void mma_fp(float c[4], const u32 a[4], u32 b0, u32 b1) {
    asm volatile(
        "mma.sync.aligned.m16n8k16.row.col.f32.f16.f16.f32 "
        "{%0,%1,%2,%3}, {%4,%5,%6,%7}, {%8,%9}, {%0,%1,%2,%3};"
        : "+f"(c[0]), "+f"(c[1]), "+f"(c[2]), "+f"(c[3])
        : "r"(a[0]), "r"(a[1]), "r"(a[2]), "r"(a[3]), "r"(b0), "r"(b1));
}
__device__ __forceinline__ void ldsm4(u32 r[4], u32 addr) {
    asm volatile("ldmatrix.sync.aligned.m8n8.x4.shared.b16 {%0,%1,%2,%3}, [%4];"
        : "=r"(r[0]), "=r"(r[1]), "=r"(r[2]), "=r"(r[3]) : "r"(addr));
}
__device__ __forceinline__ void ldsm4t(u32 r[4], u32 addr) {
    asm volatile("ldmatrix.sync.aligned.m8n8.x4.trans.shared.b16 {%0,%1,%2,%3}, [%4];"
        : "=r"(r[0]), "=r"(r[1]), "=r"(r[2]), "=r"(r[3]) : "r"(addr));
}
__device__ __forceinline__ void cp16(u32 dst, const void* src) {
    asm volatile("cp.async.cg.shared.global [%0], [%1], 16;" :: "r"(dst), "l"(src));
}
#define CP_COMMIT() asm volatile("cp.async.commit_group;" ::: "memory")
#define CP_WAIT0()  asm volatile("cp.async.wait_group 0;" ::: "memory")

#define PKA 40
#define PNB 136

// ---------------------------------------------------------------------------
// Pre-convert: w_qkv fp32 -> fp16 (q rows scaled by QSCALE*LOG2E); x -> fp16
// ---------------------------------------------------------------------------
__global__ __launch_bounds__(256) void conv_w(const float* __restrict__ w)
{
    int i4 = blockIdx.x * 256 + threadIdx.x;          // 196608 total
    float4 v = ((const float4*)w)[i4];
    float sc = (i4 < (HID * CDIM / 4)) ? (QSCALE * LOG2E) : 1.0f;
    ((uint2*)g_w16)[i4] = make_uint2(pack_f16x2(v.x * sc, v.y * sc),
                                     pack_f16x2(v.z * sc, v.w * sc));
}
__global__ __launch_bounds__(256) void conv_x(const float* __restrict__ x)
{
    size_t i4 = (size_t)blockIdx.x * 256 + threadIdx.x;  // 1048576 total
    float4 v = ((const float4*)x)[i4];
    ((uint2*)g_x16)[i4] = make_uint2(pack_f16x2(v.x, v.y), pack_f16x2(v.z, v.w));
}

// ---------------------------------------------------------------------------
// qkv GEMM: fp16 operands, cp.async 2-stage pipeline, fused fp16 epilogue:
//   q/k tiles -> smem transpose -> g_qh/g_kh [b][h][l][d]
//   v tiles   -> direct [b][h][d][l]
// CTA 128(features) x 128(l), TK=32, 8 warps (4m x 2n).
// ---------------------------------------------------------------------------
#define QA_SZ (128 * PKA * 2)    // 10240
#define QB_SZ (32 * PNB * 2)     // 8704
#define Q_STG (QA_SZ + QB_SZ)    // 18944
#define QKV_SM (2 * Q_STG)       // 37888 (transpose epilogue needs 34816)

__global__ void __launch_bounds__(256, 2) gemm_qkv(void)
{
    __shared__ __align__(16) char smraw[QKV_SM];
    const u32 sb = smem_u32(smraw);

    const int tid = threadIdx.x;
    const int lane = tid & 31, wid = tid >> 5;
    const int lam = lane & 3, g = lane >> 2;
    const int wm = (wid & 3) * 32, wn = (wid >> 2) * 64;
    const int m0 = blockIdx.y * 128, n0 = blockIdx.x * 128;
    const int bb = blockIdx.z;

    const uint16_t* Aw = g_w16;
    const uint16_t* Bx = g_x16 + (size_t)bb * CDIM * LSEQ;
    const int fr = lane & 15, fc = (lane >> 4) * 8;

    auto issue = [&](int st, int k0) {
        u32 base = sb + st * Q_STG;
#pragma unroll
        for (int j = 0; j < 2; j++) {
            int c = tid * 2 + j;                        // 0..511
            int ar_ = c >> 2, ac = c & 3;               // A: m row, 16B chunk
            cp16(base + (u32)(ar_ * PKA + ac * 8) * 2,
                 Aw + (size_t)(m0 + ar_) * CDIM + k0 + ac * 8);
            int br_ = c >> 4, bc = c & 15;              // B: k row, 16B chunk
            cp16(base + QA_SZ + (u32)(br_ * PNB + bc * 8) * 2,
                 Bx + (size_t)(k0 + br_) * LSEQ + n0 + bc * 8);
        }
    };

    float acc[2][8][4];
#pragma unroll
    for (int mt = 0; mt < 2; mt++)
#pragma unroll
        for (int nt = 0; nt < 8; nt++)
#pragma unroll
            for (int r = 0; r < 4; r++) acc[mt][nt][r] = 0.f;

    issue(0, 0);
    CP_COMMIT();

    for (int s = 0; s < 16; s++) {
        CP_WAIT0();
        __syncthreads();
        if (s < 15) { issue((s + 1) & 1, (s + 1) * 32); CP_COMMIT(); }

        const u32 aB = sb + (s & 1) * Q_STG;
        const u32 bB = aB + QA_SZ;

#pragma unroll
        for (int ks = 0; ks < 2; ks++) {
            u32 ahf[2][4];
#pragma unroll
            for (int mt = 0; mt < 2; mt++) {
                u32 off = (u32)((wm + mt * 16 + fr) * PKA + ks * 16 + fc) * 2;
                ldsm4(ahf[mt], aB + off);
            }
#pragma unroll
            for (int ntp = 0; ntp < 4; ntp++) {
                u32 bhf[4];
                u32 off = (u32)((ks * 16 + fr) * PNB + wn + ntp * 16 + fc) * 2;
                ldsm4t(bhf, bB + off);
#pragma unroll
                for (int mt = 0; mt < 2; mt++) {
                    mma_fp(acc[mt][2 * ntp],     ahf[mt], bhf[0], bhf[1]);
                    mma_fp(acc[mt][2 * ntp + 1], ahf[mt], bhf[2], bhf[3]);
                }
            }
        }
        __syncthreads();
    }

    if (m0 < 1024) {
        // ---- q/k tile: fp16 transpose via smem, then [b][h][l][d] rows
        uint16_t* Ts = (uint16_t*)smraw;             // [n 128][m 128] pitch 136
#pragma unroll
        for (int mt = 0; mt < 2; mt++)
#pragma unroll
            for (int r = 0; r < 2; r++) {
                int ml = wm + mt * 16 + g + r * 8;
#pragma unroll
                for (int nt = 0; nt < 8; nt++) {
                    int nl = wn + nt * 8 + lam * 2;
                    u32 w = pack_f16x2(acc[mt][nt][r * 2], acc[mt][nt][r * 2 + 1]);
                    Ts[nl * 136 + ml]       = (uint16_t)(w & 0xffffu);
                    Ts[(nl + 1) * 136 + ml] = (uint16_t)(w >> 16);
                }
            }
        __syncthreads();
        uint16_t* dstq = (m0 < 512) ? g_qh : g_kh;
        const int ob = m0 & 511;
#pragma unroll
        for (int it = tid; it < 2048; it += 256) {
            int nl = it >> 4, mc = (it & 15) * 8;
            int o = ob + mc;
            int h = o >> 6, d = o & 63;
            uint4 v = *(uint4*)&Ts[nl * 136 + mc];
            *(uint4*)(dstq + (((size_t)(bb * 8 + h) * LSEQ) + n0 + nl) * 64 + d) = v;
        }
    } else {
        // ---- v tile: direct fp16 [b][h][d][l]
        const int o0 = m0 - 1024;
#pragma unroll
        for (int mt = 0; mt < 2; mt++)
#pragma unroll
            for (int r = 0; r < 2; r++) {
                int o = o0 + wm + mt * 16 + g + r * 8;
                int h = o >> 6, d = o & 63;
                uint16_t* dv = g_vh + ((size_t)(bb * 8 + h) * 64 + d) * LSEQ + n0 + wn;
#pragma unroll
                for (int nt = 0; nt < 8; nt++)
                    *(u32*)(dv + nt * 8 + lam * 2) =
                        pack_f16x2(acc[mt][nt][r * 2], acc[mt][nt][r * 2 + 1]);
            }
    }
}

// ---------------------------------------------------------------------------
// bf16-split GEMM (3-term, fp32-grade) for the output projection.
// ---------------------------------------------------------------------------
__global__ void __launch_bounds__(256, 2) gemm_bf(
    const float* __restrict__ A, const float* __restrict__ Bm,
    float* __restrict__ C, const float* __restrict__ bias,
    int M, int N, int K, long strideB, long strideC)
{
    __shared__ uint16_t Ah[128 * PKA], Al[128 * PKA];
    __shared__ uint16_t Bh[32 * PNB],  Bl[32 * PNB];

    const int tid = threadIdx.x;
    const int lane = tid & 31, wid = tid >> 5;
    const int lam = lane & 3;
    const int wm = (wid & 3) * 32, wn = (wid >> 2) * 64;
    const int m0 = blockIdx.y * 128, n0 = blockIdx.x * 128;
    const float* Bb = Bm + (size_t)blockIdx.z * strideB;
    float* Cb = C + (size_t)blockIdx.z * strideC;

    const int ar = tid >> 1, akb = (tid & 1) * 16;
    const int br = tid >> 3, bnb = (tid & 7) * 16;
    const int fr = lane & 15, fc = (lane >> 4) * 8;

    float acc[2][8][4];
#pragma unroll
    for (int mt = 0; mt < 2; mt++)
#pragma unroll
        for (int nt = 0; nt < 8; nt++)
#pragma unroll
            for (int r = 0; r < 4; r++) acc[mt][nt][r] = 0.f;

    for (int k0 = 0; k0 < K; k0 += 32) {
        const float* Ag = A + (size_t)(m0 + ar) * K + k0 + akb;
#pragma unroll
        for (int q = 0; q < 4; q++) {
            float4 v = *(const float4*)(Ag + q * 4);
            u32 h0, l0, h1, l1;
            split_pair(v.x, v.y, h0, l0);
            split_pair(v.z, v.w, h1, l1);
            int kk = akb + q * 4;
            *(u32*)&Ah[ar * PKA + kk]     = h0;
            *(u32*)&Ah[ar * PKA + kk + 2] = h1;
            *(u32*)&Al[ar * PKA + kk]     = l0;
            *(u32*)&Al[ar * PKA + kk + 2] = l1;
        }
        const float* Bg = Bb + (size_t)(k0 + br) * N + n0 + bnb;
#pragma unroll
        for (int q = 0; q < 4; q++) {
            float4 v = *(const float4*)(Bg + q * 4);
            u32 h0, l0, h1, l1;
            split_pair(v.x, v.y, h0, l0);
            split_pair(v.z, v.w, h1, l1);
            int nn = bnb + q * 4;
            *(u32*)&Bh[br * PNB + nn]     = h0;
            *(u32*)&Bh[br * PNB + nn + 2] = h1;
            *(u32*)&Bl[br * PNB + nn]     = l0;
            *(u32*)&Bl[br * PNB + nn + 2] = l1;
        }
        __syncthreads();

#pragma unroll
        for (int ks = 0; ks < 2; ks++) {
            u32 ahf[2][4], alf[2][4];
#pragma unroll
            for (int mt = 0; mt < 2; mt++) {
                u32 off = (u32)((wm + mt * 16 + fr) * PKA + ks * 16 + fc) * 2;
                ldsm4(ahf[mt], smem_u32(Ah) + off);
                ldsm4(alf[mt], smem_u32(Al) + off);
            }
#pragma unroll
            for (int ntp = 0; ntp < 4; ntp++) {
                u32 bhf[4], blf[4];
                u32 off = (u32)((ks * 16 + fr) * PNB + wn + ntp * 16 + fc) * 2;
                ldsm4t(bhf, smem_u32(Bh) + off);
                ldsm4t(blf, smem_u32(Bl) + off);
#pragma unroll
                for (int mt = 0; mt < 2; mt++) {
                    mma_bf(acc[mt][2 * ntp],     ahf[mt], bhf[0], bhf[1]);
                    mma_bf(acc[mt][2 * ntp + 1], ahf[mt], bhf[2], bhf[3]);
                    mma_bf(acc[mt][2 * ntp],     ahf[mt], blf[0], blf[1]);
                    mma_bf(acc[mt][2 * ntp + 1], ahf[mt], blf[2], blf[3]);
                    mma_bf(acc[mt][2 * ntp],     alf[mt], bhf[0], bhf[1]);
                    mma_bf(acc[mt][2 * ntp + 1], alf[mt], bhf[2], bhf[3]);
                }
            }
        }
        __syncthreads();
    }

    const int g = lane >> 2;
#pragma unroll
    for (int mt = 0; mt < 2; mt++) {
#pragma unroll
        for (int r = 0; r < 2; r++) {
            int m = m0 + wm + mt * 16 + g + r * 8;
            float bv = bias ? bias[m] : 0.0f;
            float* Crow = Cb + (size_t)m * N + n0 + wn;
#pragma unroll
            for (int nt = 0; nt < 8; nt++) {
                float2 o;
                o.x = acc[mt][nt][r * 2 + 0] + bv;
                o.y = acc[mt][nt][r * 2 + 1] + bv;
                *(float2*)(Crow + nt * 8 + lam * 2) = o;
            }
        }
    }
}

// ---------------------------------------------------------------------------
// Flash attention v6: fp16 single-term, 64-key chunks, 2 CTAs/SM,
// ex2 softmax (q pre-scaled by log2e), row sums via ones-column MMA.
// ---------------------------------------------------------------------------
#define PD  72
#define POT 132

#define F_QH 0
#define F_KH (128 * PD * 2)
#define F_V  (F_KH + 64 * PD * 2)
#define FLASH_SMEM (F_V + 64 * PD * 2)   // 36864 B

__global__ void __launch_bounds__(256, 2) flash_mma(float* __restrict__ att)
{
    extern __shared__ char smc[];
    uint16_t* Qh = (uint16_t*)(smc + F_QH);
    uint16_t* Kh = (uint16_t*)(smc + F_KH);
    uint16_t* Vs = (uint16_t*)(smc + F_V);

    const int tid = threadIdx.x;
    const int lane = tid & 31, wid = tid >> 5;
    const int g = lane >> 2, lam = lane & 3;
    const int fr = lane & 15, fc = (lane >> 4) * 8;
    const int bh = blockIdx.y;
    const int q0 = blockIdx.x * 128;

    const uint16_t* kh = g_kh + (size_t)bh * LSEQ * DHEAD;
    const uint16_t* vh = g_vh + (size_t)bh * DHEAD * LSEQ;

    {
        const uint16_t* qh = g_qh + ((size_t)bh * LSEQ + q0) * DHEAD;
#pragma unroll
        for (int it = tid; it < 1024; it += 256) {
            int r = it >> 3, c = (it & 7) * 8;
            *(uint4*)&Qh[r * PD + c] = *(const uint4*)(qh + (size_t)r * 64 + c);
        }
    }

    float o[8][4];
#pragma unroll
    for (int nt = 0; nt < 8; nt++)
#pragma unroll
        for (int r = 0; r < 4; r++) o[nt][r] = 0.f;

    // ones-column B fragment (B[k][0]=1, else 0): lanes with n==g==0 hold 1s
    const u32 onesb = (g == 0) ? 0x3C003C00u : 0u;
    float sacc[4] = {0.f, 0.f, 0.f, 0.f};   // col0 = row sums (rows g, g+8)

    const u32 qB = smem_u32(Qh), kB = smem_u32(Kh), vB = smem_u32(Vs);

    for (int n0 = 0; n0 < LSEQ; n0 += 64) {
        __syncthreads();
#pragma unroll
        for (int it = tid; it < 512; it += 256) {
            int r = it >> 3, c = (it & 7) * 8;
            *(uint4*)&Kh[r * PD + c] =
                *(const uint4*)(kh + (size_t)(n0 + r) * 64 + c);
            *(uint4*)&Vs[r * PD + c] =
                *(const uint4*)(vh + (size_t)r * LSEQ + n0 + c);
        }
        __syncthreads();

        float s[8][4];
#pragma unroll
        for (int nt = 0; nt < 8; nt++)
#pragma unroll
            for (int r = 0; r < 4; r++) s[nt][r] = 0.f;

#pragma unroll
        for (int ks = 0; ks < 4; ks++) {
            u32 qf[4];
            u32 qoff = (u32)((wid * 16 + fr) * PD + ks * 16 + fc) * 2;
            ldsm4(qf, qB + qoff);
#pragma unroll
            for (int ntp = 0; ntp < 4; ntp++) {
                u32 kf[4];
                u32 koff = (u32)((ntp * 16 + fr) * PD + ks * 16 + fc) * 2;
                ldsm4(kf, kB + koff);
                mma_fp(s[2 * ntp],     qf, kf[0], kf[2]);
                mma_fp(s[2 * ntp + 1], qf, kf[1], kf[3]);
            }
        }

        // exp2 (q pre-scaled by log2e); sums come from the ones-MMA below
#pragma unroll
        for (int nt = 0; nt < 8; nt++) {
            s[nt][0] = ex2f(s[nt][0]);
            s[nt][1] = ex2f(s[nt][1]);
            s[nt][2] = ex2f(s[nt][2]);
            s[nt][3] = ex2f(s[nt][3]);
        }

#pragma unroll
        for (int ks2 = 0; ks2 < 4; ks2++) {
            int t = ks2 * 2;
            u32 pa[4];
            pa[0] = pack_f16x2(s[t][0],     s[t][1]);
            pa[1] = pack_f16x2(s[t][2],     s[t][3]);
            pa[2] = pack_f16x2(s[t + 1][0], s[t + 1][1]);
            pa[3] = pack_f16x2(s[t + 1][2], s[t + 1][3]);
            mma_fp(sacc, pa, onesb, onesb);   // row sums (fp16 p, fp32 accum)
#pragma unroll
            for (int dp = 0; dp < 4; dp++) {
                u32 vf[4];
                u32 voff = (u32)((dp * 16 + fr) * PD + ks2 * 16 + fc) * 2;
                ldsm4(vf, vB + voff);
                mma_fp(o[2 * dp],     pa, vf[0], vf[2]);
                mma_fp(o[2 * dp + 1], pa, vf[1], vf[3]);
            }
        }
    }

    // broadcast row sums from each quad's lam==0 lane (col 0 of sacc)
    const float rsum0 = __shfl_sync(0xffffffffu, sacc[0], lane & ~3);
    const float rsum1 = __shfl_sync(0xffffffffu, sacc[2], lane & ~3);
    const float inv0 = 1.0f / rsum0, inv1 = 1.0f / rsum1;

    float* Ot = (float*)smc;
    __syncthreads();
#pragma unroll
    for (int nt = 0; nt < 8; nt++) {
        int d = nt * 8 + 2 * lam;
        int q = wid * 16 + g;
        Ot[d * POT + q]           = o[nt][0] * inv0;
        Ot[(d + 1) * POT + q]     = o[nt][1] * inv0;
        Ot[d * POT + q + 8]       = o[nt][2] * inv1;
        Ot[(d + 1) * POT + q + 8] = o[nt][3] * inv1;
    }
    __syncthreads();
    const int b = bh >> 3, h = bh & 7;
    float* dst = att + ((size_t)b * HID + h * DHEAD) * LSEQ + q0;
#pragma unroll
    for (int it = tid; it < 2048; it += 256) {
        int d = it >> 5, c = (it & 31) * 4;
        *(float4*)(dst + (size_t)d * LSEQ + c) = *(float4*)&Ot[d * POT + c];
    }
}

// ---------------------------------------------------------------------------
extern "C" void kernel_launch(void* const* d_in, const int* in_sizes, int n_in,
                              void* d_out, int out_size)
{
    const float* x     = (const float*)d_in[0];
    const float* w_qkv = (const float*)d_in[1];
    const float* w_out = (const float*)d_in[2];
    const float* b_out = (const float*)d_in[3];
    float* out = (float*)d_out;

    float* att;
    cudaGetSymbolAddress((void**)&att, g_att);

    cudaFuncSetAttribute(flash_mma,
        cudaFuncAttributeMaxDynamicSharedMemorySize, FLASH_SMEM);

    dim3 t(256);
    // 0) fp16 pre-conversion (q-scale * log2e folded into w_qkv q rows)
    conv_w<<<(O3 * CDIM / 4) / 256, t>>>(w_qkv);
    conv_x<<<(int)(((size_t)B_ * CDIM * LSEQ / 4) / 256), t>>>(x);

    // 1) fused qkv projection (cp.async pipelined) + fp16 layout epilogue
    gemm_qkv<<<dim3(LSEQ / 128, O3 / 128, B_), t>>>();

    // 2) flash attention (fp16, ex2 softmax, MMA row sums, 2 CTAs/SM)
    flash_mma<<<dim3(LSEQ / 128, B_ * HEADS_), t, FLASH_SMEM>>>(att);

    // 3) out = w_out @ att + b_out  (3-term bf16, fp32-grade)
    gemm_bf<<<dim3(LSEQ / 128, CDIM / 128, B_), t>>>(
        w_out, att, out, b_out, CDIM, LSEQ, HID,
        (long)HID * LSEQ, (long)CDIM * LSEQ);
}

// round 15
// speedup vs baseline: 1.3994x; 1.3994x over previous
#include <cuda_runtime.h>
#include <stdint.h>

#define B_     4
#define CDIM   512
#define LSEQ   2048
#define HEADS_ 8
#define DHEAD  64
#define HID    512
#define O3     1536
#define QSCALE 0.125f
#define LOG2E  1.44269504088896f

typedef uint32_t u32;

// ------------------------- scratch (device globals) -------------------------
__device__ float    g_att[(size_t)B_ * HID * LSEQ];   // [b][h*64+d][l]
__device__ uint16_t g_qh[(size_t)B_ * HEADS_ * LSEQ * DHEAD]; // [b][h][l][d] fp16 (q*log2e*scale)
__device__ uint16_t g_kh[(size_t)B_ * HEADS_ * LSEQ * DHEAD]; // fp16
__device__ uint16_t g_vh[(size_t)B_ * HEADS_ * DHEAD * LSEQ]; // [b][h][d][l] fp16

// ------------------------------- helpers -------------------------------------
__device__ __forceinline__ u32 smem_u32(const void* p) {
    u32 a; asm("{ .reg .u64 t; cvta.to.shared.u64 t, %1; cvt.u32.u64 %0, t; }"
               : "=r"(a) : "l"(p));
    return a;
}
__device__ __forceinline__ u32 pack_bf16x2(float a, float b) {   // lo=a, hi=b
    u32 r; asm("cvt.rn.bf16x2.f32 %0, %1, %2;" : "=r"(r) : "f"(b), "f"(a));
    return r;
}
__device__ __forceinline__ u32 pack_f16x2(float a, float b) {    // lo=a, hi=b
    u32 r; asm("cvt.rn.f16x2.f32 %0, %1, %2;" : "=r"(r) : "f"(b), "f"(a));
    return r;
}
__device__ __forceinline__ float ex2f(float x) {
    float y; asm("ex2.approx.f32 %0, %1;" : "=f"(y) : "f"(x)); return y;
}
__device__ __forceinline__ float bf_lo(u32 w) { return __uint_as_float(w << 16); }
__device__ __forceinline__ float bf_hi(u32 w) { return __uint_as_float(w & 0xffff0000u); }
__device__ __forceinline__ void split_pair(float a, float b, u32& hw, u32& lw) {
    hw = pack_bf16x2(a, b);
    lw = pack_bf16x2(a - bf_lo(hw), b - bf_hi(hw));
}
__device__ __forceinline__ void mma_bf(float c[4], const u32 a[4], u32 b0, u32 b1) {
    asm volatile(
        "mma.sync.aligned.m16n8k16.row.col.f32.bf16.bf16.f32 "
        "{%0,%1,%2,%3}, {%4,%5,%6,%7}, {%8,%9}, {%0,%1,%2,%3};"
        : "+f"(c[0]), "+f"(c[1]), "+f"(c[2]), "+f"(c[3])
        : "r"(a[0]), "r"(a[1]), "r"(a[2]), "r"(a[3]), "r"(b0), "r"(b1));
}
__device__ __forceinline__ void mma_fp(float c[4], const u32 a[4], u32 b0, u32 b1) {
    asm volatile(
        "mma.sync.aligned.m16n8k16.row.col.f32.f16.f16.f32 "
        "{%0,%1,%2,%3}, {%4,%5,%6,%7}, {%8,%9}, {%0,%1,%2,%3};"
        : "+f"(c[0]), "+f"(c[1]), "+f"(c[2]), "+f"(c[3])
        : "r"(a[0]), "r"(a[1]), "r"(a[2]), "r"(a[3]), "r"(b0), "r"(b1));
}
__device__ __forceinline__ void ldsm4(u32 r[4], u32 addr) {
    asm volatile("ldmatrix.sync.aligned.m8n8.x4.shared.b16 {%0,%1,%2,%3}, [%4];"
        : "=r"(r[0]), "=r"(r[1]), "=r"(r[2]), "=r"(r[3]) : "r"(addr));
}
__device__ __forceinline__ void ldsm4t(u32 r[4], u32 addr) {
    asm volatile("ldmatrix.sync.aligned.m8n8.x4.trans.shared.b16 {%0,%1,%2,%3}, [%4];"
        : "=r"(r[0]), "=r"(r[1]), "=r"(r[2]), "=r"(r[3]) : "r"(addr));
}

#define PKA 40
#define PNB 136

// ---------------------------------------------------------------------------
// qkv GEMM (R13 proven): single-term fp16, fused epilogue:
//   q/k tiles -> smem fp16 transpose -> g_qh/g_kh [b][h][l][d]
//   v tiles   -> direct fp16 [b][h][d][l]
// q rows pre-scaled by QSCALE*LOG2E (flash uses raw ex2).
// ---------------------------------------------------------------------------
#define QKV_SM 34816

__global__ void __launch_bounds__(256, 2) gemm_qkv(
    const float* __restrict__ A, const float* __restrict__ Bm)
{
    __shared__ __align__(16) char smraw[QKV_SM];
    uint16_t* Ah = (uint16_t*)smraw;
    uint16_t* Bh = (uint16_t*)(smraw + 128 * PKA * 2);

    const int tid = threadIdx.x;
    const int lane = tid & 31, wid = tid >> 5;
    const int lam = lane & 3, g = lane >> 2;
    const int wm = (wid & 3) * 32, wn = (wid >> 2) * 64;
    const int m0 = blockIdx.y * 128, n0 = blockIdx.x * 128;
    const int bb = blockIdx.z;
    const float* Bb = Bm + (size_t)bb * CDIM * LSEQ;

    const int ar = tid >> 1, akb = (tid & 1) * 16;
    const int br = tid >> 3, bnb = (tid & 7) * 16;
    const int fr = lane & 15, fc = (lane >> 4) * 8;

    float acc[2][8][4];
#pragma unroll
    for (int mt = 0; mt < 2; mt++)
#pragma unroll
        for (int nt = 0; nt < 8; nt++)
#pragma unroll
            for (int r = 0; r < 4; r++) acc[mt][nt][r] = 0.f;

    for (int k0 = 0; k0 < CDIM; k0 += 32) {
        const float* Ag = A + (size_t)(m0 + ar) * CDIM + k0 + akb;
#pragma unroll
        for (int q = 0; q < 4; q++) {
            float4 v = *(const float4*)(Ag + q * 4);
            int kk = akb + q * 4;
            *(u32*)&Ah[ar * PKA + kk]     = pack_f16x2(v.x, v.y);
            *(u32*)&Ah[ar * PKA + kk + 2] = pack_f16x2(v.z, v.w);
        }
        const float* Bg = Bb + (size_t)(k0 + br) * LSEQ + n0 + bnb;
#pragma unroll
        for (int q = 0; q < 4; q++) {
            float4 v = *(const float4*)(Bg + q * 4);
            int nn = bnb + q * 4;
            *(u32*)&Bh[br * PNB + nn]     = pack_f16x2(v.x, v.y);
            *(u32*)&Bh[br * PNB + nn + 2] = pack_f16x2(v.z, v.w);
        }
        __syncthreads();

#pragma unroll
        for (int ks = 0; ks < 2; ks++) {
            u32 ahf[2][4];
#pragma unroll
            for (int mt = 0; mt < 2; mt++) {
                u32 off = (u32)((wm + mt * 16 + fr) * PKA + ks * 16 + fc) * 2;
                ldsm4(ahf[mt], smem_u32(Ah) + off);
            }
#pragma unroll
            for (int ntp = 0; ntp < 4; ntp++) {
                u32 bhf[4];
                u32 off = (u32)((ks * 16 + fr) * PNB + wn + ntp * 16 + fc) * 2;
                ldsm4t(bhf, smem_u32(Bh) + off);
#pragma unroll
                for (int mt = 0; mt < 2; mt++) {
                    mma_fp(acc[mt][2 * ntp],     ahf[mt], bhf[0], bhf[1]);
                    mma_fp(acc[mt][2 * ntp + 1], ahf[mt], bhf[2], bhf[3]);
                }
            }
        }
        __syncthreads();
    }

    if (m0 < 1024) {
        const float sc = (m0 < 512) ? (QSCALE * LOG2E) : 1.0f;
        uint16_t* Ts = (uint16_t*)smraw;             // [n 128][m 128] pitch 136
#pragma unroll
        for (int mt = 0; mt < 2; mt++)
#pragma unroll
            for (int r = 0; r < 2; r++) {
                int ml = wm + mt * 16 + g + r * 8;
#pragma unroll
                for (int nt = 0; nt < 8; nt++) {
                    int nl = wn + nt * 8 + lam * 2;
                    u32 w = pack_f16x2(acc[mt][nt][r * 2] * sc,
                                       acc[mt][nt][r * 2 + 1] * sc);
                    Ts[nl * 136 + ml]       = (uint16_t)(w & 0xffffu);
                    Ts[(nl + 1) * 136 + ml] = (uint16_t)(w >> 16);
                }
            }
        __syncthreads();
        uint16_t* dstq = (m0 < 512) ? g_qh : g_kh;
        const int ob = m0 & 511;
#pragma unroll
        for (int it = tid; it < 2048; it += 256) {
            int nl = it >> 4, mc = (it & 15) * 8;
            int o = ob + mc;
            int h = o >> 6, d = o & 63;
            uint4 v = *(uint4*)&Ts[nl * 136 + mc];
            *(uint4*)(dstq + (((size_t)(bb * 8 + h) * LSEQ) + n0 + nl) * 64 + d) = v;
        }
    } else {
        const int o0 = m0 - 1024;
#pragma unroll
        for (int mt = 0; mt < 2; mt++)
#pragma unroll
            for (int r = 0; r < 2; r++) {
                int o = o0 + wm + mt * 16 + g + r * 8;
                int h = o >> 6, d = o & 63;
                uint16_t* dv = g_vh + ((size_t)(bb * 8 + h) * 64 + d) * LSEQ + n0 + wn;
#pragma unroll
                for (int nt = 0; nt < 8; nt++)
                    *(u32*)(dv + nt * 8 + lam * 2) =
                        pack_f16x2(acc[mt][nt][r * 2], acc[mt][nt][r * 2 + 1]);
            }
    }
}

// ---------------------------------------------------------------------------
// bf16-split GEMM (3-term, fp32-grade) for the output projection. (R13 proven)
// ---------------------------------------------------------------------------
__global__ void __launch_bounds__(256, 2) gemm_bf(
    const float* __restrict__ A, const float* __restrict__ Bm,
    float* __restrict__ C, const float* __restrict__ bias,
    int M, int N, int K, long strideB, long strideC)
{
    __shared__ uint16_t Ah[128 * PKA], Al[128 * PKA];
    __shared__ uint16_t Bh[32 * PNB],  Bl[32 * PNB];

    const int tid = threadIdx.x;
    const int lane = tid & 31, wid = tid >> 5;
    const int lam = lane & 3;
    const int wm = (wid & 3) * 32, wn = (wid >> 2) * 64;
    const int m0 = blockIdx.y * 128, n0 = blockIdx.x * 128;
    const float* Bb = Bm + (size_t)blockIdx.z * strideB;
    float* Cb = C + (size_t)blockIdx.z * strideC;

    const int ar = tid >> 1, akb = (tid & 1) * 16;
    const int br = tid >> 3, bnb = (tid & 7) * 16;
    const int fr = lane & 15, fc = (lane >> 4) * 8;

    float acc[2][8][4];
#pragma unroll
    for (int mt = 0; mt < 2; mt++)
#pragma unroll
        for (int nt = 0; nt < 8; nt++)
#pragma unroll
            for (int r = 0; r < 4; r++) acc[mt][nt][r] = 0.f;

    for (int k0 = 0; k0 < K; k0 += 32) {
        const float* Ag = A + (size_t)(m0 + ar) * K + k0 + akb;
#pragma unroll
        for (int q = 0; q < 4; q++) {
            float4 v = *(const float4*)(Ag + q * 4);
            u32 h0, l0, h1, l1;
            split_pair(v.x, v.y, h0, l0);
            split_pair(v.z, v.w, h1, l1);
            int kk = akb + q * 4;
            *(u32*)&Ah[ar * PKA + kk]     = h0;
            *(u32*)&Ah[ar * PKA + kk + 2] = h1;
            *(u32*)&Al[ar * PKA + kk]     = l0;
            *(u32*)&Al[ar * PKA + kk + 2] = l1;
        }
        const float* Bg = Bb + (size_t)(k0 + br) * N + n0 + bnb;
#pragma unroll
        for (int q = 0; q < 4; q++) {
            float4 v = *(const float4*)(Bg + q * 4);
            u32 h0, l0, h1, l1;
            split_pair(v.x, v.y, h0, l0);
            split_pair(v.z, v.w, h1, l1);
            int nn = bnb + q * 4;
            *(u32*)&Bh[br * PNB + nn]     = h0;
            *(u32*)&Bh[br * PNB + nn + 2] = h1;
            *(u32*)&Bl[br * PNB + nn]     = l0;
            *(u32*)&Bl[br * PNB + nn + 2] = l1;
        }
        __syncthreads();

#pragma unroll
        for (int ks = 0; ks < 2; ks++) {
            u32 ahf[2][4], alf[2][4];
#pragma unroll
            for (int mt = 0; mt < 2; mt++) {
                u32 off = (u32)((wm + mt * 16 + fr) * PKA + ks * 16 + fc) * 2;
                ldsm4(ahf[mt], smem_u32(Ah) + off);
                ldsm4(alf[mt], smem_u32(Al) + off);
            }
#pragma unroll
            for (int ntp = 0; ntp < 4; ntp++) {
                u32 bhf[4], blf[4];
                u32 off = (u32)((ks * 16 + fr) * PNB + wn + ntp * 16 + fc) * 2;
                ldsm4t(bhf, smem_u32(Bh) + off);
                ldsm4t(blf, smem_u32(Bl) + off);
#pragma unroll
                for (int mt = 0; mt < 2; mt++) {
                    mma_bf(acc[mt][2 * ntp],     ahf[mt], bhf[0], bhf[1]);
                    mma_bf(acc[mt][2 * ntp + 1], ahf[mt], bhf[2], bhf[3]);
                    mma_bf(acc[mt][2 * ntp],     ahf[mt], blf[0], blf[1]);
                    mma_bf(acc[mt][2 * ntp + 1], ahf[mt], blf[2], blf[3]);
                    mma_bf(acc[mt][2 * ntp],     alf[mt], bhf[0], bhf[1]);
                    mma_bf(acc[mt][2 * ntp + 1], alf[mt], bhf[2], bhf[3]);
                }
            }
        }
        __syncthreads();
    }

    const int g = lane >> 2;
#pragma unroll
    for (int mt = 0; mt < 2; mt++) {
#pragma unroll
        for (int r = 0; r < 2; r++) {
            int m = m0 + wm + mt * 16 + g + r * 8;
            float bv = bias ? bias[m] : 0.0f;
            float* Crow = Cb + (size_t)m * N + n0 + wn;
#pragma unroll
            for (int nt = 0; nt < 8; nt++) {
                float2 o;
                o.x = acc[mt][nt][r * 2 + 0] + bv;
                o.y = acc[mt][nt][r * 2 + 1] + bv;
                *(float2*)(Crow + nt * 8 + lam * 2) = o;
            }
        }
    }
}

// ---------------------------------------------------------------------------
// Flash attention v5 + K/V register prefetch: fp16 single-term, 64-key
// chunks, 2 CTAs/SM, ex2 softmax, scalar FADD row sums (R13 proven math).
// ---------------------------------------------------------------------------
#define PD  72
#define POT 132

#define F_QH 0
#define F_KH (128 * PD * 2)
#define F_V  (F_KH + 64 * PD * 2)
#define FLASH_SMEM (F_V + 64 * PD * 2)   // 36864 B

__global__ void __launch_bounds__(256, 2) flash_mma(float* __restrict__ att)
{
    extern __shared__ char smc[];
    uint16_t* Qh = (uint16_t*)(smc + F_QH);
    uint16_t* Kh = (uint16_t*)(smc + F_KH);
    uint16_t* Vs = (uint16_t*)(smc + F_V);

    const int tid = threadIdx.x;
    const int lane = tid & 31, wid = tid >> 5;
    const int g = lane >> 2, lam = lane & 3;
    const int fr = lane & 15, fc = (lane >> 4) * 8;
    const int bh = blockIdx.y;
    const int q0 = blockIdx.x * 128;

    const uint16_t* kh = g_kh + (size_t)bh * LSEQ * DHEAD;
    const uint16_t* vh = g_vh + (size_t)bh * DHEAD * LSEQ;

    // staging coords: rows sr, sr+32; cols sc_..sc_+7
    const int sr = tid >> 3, sc_ = (tid & 7) * 8;

    // prefetch registers for next chunk's K/V
    uint4 kr0, kr1, vr0, vr1;
    auto loadKV = [&](int n0) {
        kr0 = *(const uint4*)(kh + (size_t)(n0 + sr) * 64 + sc_);
        kr1 = *(const uint4*)(kh + (size_t)(n0 + sr + 32) * 64 + sc_);
        vr0 = *(const uint4*)(vh + (size_t)sr * LSEQ + n0 + sc_);
        vr1 = *(const uint4*)(vh + (size_t)(sr + 32) * LSEQ + n0 + sc_);
    };

    loadKV(0);

    // stage Q [128 q][64 d] fp16 (overlaps with K/V LDGs in flight)
    {
        const uint16_t* qh = g_qh + ((size_t)bh * LSEQ + q0) * DHEAD;
#pragma unroll
        for (int it = tid; it < 1024; it += 256) {
            int r = it >> 3, c = (it & 7) * 8;
            *(uint4*)&Qh[r * PD + c] = *(const uint4*)(qh + (size_t)r * 64 + c);
        }
    }

    float o[8][4];
#pragma unroll
    for (int nt = 0; nt < 8; nt++)
#pragma unroll
        for (int r = 0; r < 4; r++) o[nt][r] = 0.f;
    float rs0 = 0.f, rs1 = 0.f;

    const u32 qB = smem_u32(Qh), kB = smem_u32(Kh), vB = smem_u32(Vs);

    for (int n0 = 0; n0 < LSEQ; n0 += 64) {
        __syncthreads();    // prior chunk's tile reads complete
        *(uint4*)&Kh[sr * PD + sc_]        = kr0;
        *(uint4*)&Kh[(sr + 32) * PD + sc_] = kr1;
        *(uint4*)&Vs[sr * PD + sc_]        = vr0;
        *(uint4*)&Vs[(sr + 32) * PD + sc_] = vr1;
        __syncthreads();
        if (n0 + 64 < LSEQ) loadKV(n0 + 64);   // LDGs overlap MMA/exp phase

        float s[8][4];
#pragma unroll
        for (int nt = 0; nt < 8; nt++)
#pragma unroll
            for (int r = 0; r < 4; r++) s[nt][r] = 0.f;

#pragma unroll
        for (int ks = 0; ks < 4; ks++) {
            u32 qf[4];
            u32 qoff = (u32)((wid * 16 + fr) * PD + ks * 16 + fc) * 2;
            ldsm4(qf, qB + qoff);
#pragma unroll
            for (int ntp = 0; ntp < 4; ntp++) {
                u32 kf[4];
                u32 koff = (u32)((ntp * 16 + fr) * PD + ks * 16 + fc) * 2;
                ldsm4(kf, kB + koff);
                mma_fp(s[2 * ntp],     qf, kf[0], kf[2]);
                mma_fp(s[2 * ntp + 1], qf, kf[1], kf[3]);
            }
        }

        // exp2 (q pre-scaled by log2e) + scalar row sums
#pragma unroll
        for (int nt = 0; nt < 8; nt++) {
            s[nt][0] = ex2f(s[nt][0]);
            s[nt][1] = ex2f(s[nt][1]);
            s[nt][2] = ex2f(s[nt][2]);
            s[nt][3] = ex2f(s[nt][3]);
            rs0 += s[nt][0] + s[nt][1];
            rs1 += s[nt][2] + s[nt][3];
        }

#pragma unroll
        for (int ks2 = 0; ks2 < 4; ks2++) {
            int t = ks2 * 2;
            u32 pa[4];
            pa[0] = pack_f16x2(s[t][0],     s[t][1]);
            pa[1] = pack_f16x2(s[t][2],     s[t][3]);
            pa[2] = pack_f16x2(s[t + 1][0], s[t + 1][1]);
            pa[3] = pack_f16x2(s[t + 1][2], s[t + 1][3]);
#pragma unroll
            for (int dp = 0; dp < 4; dp++) {
                u32 vf[4];
                u32 voff = (u32)((dp * 16 + fr) * PD + ks2 * 16 + fc) * 2;
                ldsm4(vf, vB + voff);
                mma_fp(o[2 * dp],     pa, vf[0], vf[2]);
                mma_fp(o[2 * dp + 1], pa, vf[1], vf[3]);
            }
        }
    }

    rs0 += __shfl_xor_sync(0xffffffffu, rs0, 1);
    rs0 += __shfl_xor_sync(0xffffffffu, rs0, 2);
    rs1 += __shfl_xor_sync(0xffffffffu, rs1, 1);
    rs1 += __shfl_xor_sync(0xffffffffu, rs1, 2);
    const float inv0 = 1.0f / rs0, inv1 = 1.0f / rs1;

    float* Ot = (float*)smc;
    __syncthreads();
#pragma unroll
    for (int nt = 0; nt < 8; nt++) {
        int d = nt * 8 + 2 * lam;
        int q = wid * 16 + g;
        Ot[d * POT + q]           = o[nt][0] * inv0;
        Ot[(d + 1) * POT + q]     = o[nt][1] * inv0;
        Ot[d * POT + q + 8]       = o[nt][2] * inv1;
        Ot[(d + 1) * POT + q + 8] = o[nt][3] * inv1;
    }
    __syncthreads();
    const int b = bh >> 3, h = bh & 7;
    float* dst = att + ((size_t)b * HID + h * DHEAD) * LSEQ + q0;
#pragma unroll
    for (int it = tid; it < 2048; it += 256) {
        int d = it >> 5, c = (it & 31) * 4;
        *(float4*)(dst + (size_t)d * LSEQ + c) = *(float4*)&Ot[d * POT + c];
    }
}

// ---------------------------------------------------------------------------
extern "C" void kernel_launch(void* const* d_in, const int* in_sizes, int n_in,
                              void* d_out, int out_size)
{
    const float* x     = (const float*)d_in[0];
    const float* w_qkv = (const float*)d_in[1];
    const float* w_out = (const float*)d_in[2];
    const float* b_out = (const float*)d_in[3];
    float* out = (float*)d_out;

    float* att;
    cudaGetSymbolAddress((void**)&att, g_att);

    cudaFuncSetAttribute(flash_mma,
        cudaFuncAttributeMaxDynamicSharedMemorySize, FLASH_SMEM);

    dim3 t(256);
    // 1) fused qkv projection + fp16 layout conversion (q pre-scaled w/ log2e)
    gemm_qkv<<<dim3(LSEQ / 128, O3 / 128, B_), t>>>(w_qkv, x);

    // 2) flash attention (fp16, ex2 softmax, K/V reg prefetch, 2 CTAs/SM)
    flash_mma<<<dim3(LSEQ / 128, B_ * HEADS_), t, FLASH_SMEM>>>(att);

    // 3) out = w_out @ att + b_out  (3-term bf16, fp32-grade)
    gemm_bf<<<dim3(LSEQ / 128, CDIM / 128, B_), t>>>(
        w_out, att, out, b_out, CDIM, LSEQ, HID,
        (long)HID * LSEQ, (long)CDIM * LSEQ);
}

// round 16
// speedup vs baseline: 1.5585x; 1.1136x over previous
#include <cuda_runtime.h>
#include <stdint.h>

#define B_     4
#define CDIM   512
#define LSEQ   2048
#define HEADS_ 8
#define DHEAD  64
#define HID    512
#define O3     1536
#define QSCALE 0.125f
#define LOG2E  1.44269504088896f

typedef uint32_t u32;

// ------------------------- scratch (device globals) -------------------------
__device__ float    g_att[(size_t)B_ * HID * LSEQ];   // [b][h*64+d][l]
__device__ uint16_t g_w16[O3 * CDIM];                 // w_qkv fp16 (q rows pre-scaled)
__device__ uint16_t g_x16[(size_t)B_ * CDIM * LSEQ];  // x fp16
__device__ uint16_t g_qh[(size_t)B_ * HEADS_ * LSEQ * DHEAD]; // [b][h][l][d] fp16
__device__ uint16_t g_kh[(size_t)B_ * HEADS_ * LSEQ * DHEAD]; // fp16
__device__ uint16_t g_vh[(size_t)B_ * HEADS_ * DHEAD * LSEQ]; // [b][h][d][l] fp16

// ------------------------------- helpers -------------------------------------
__device__ __forceinline__ u32 smem_u32(const void* p) {
    u32 a; asm("{ .reg .u64 t; cvta.to.shared.u64 t, %1; cvt.u32.u64 %0, t; }"
               : "=r"(a) : "l"(p));
    return a;
}
__device__ __forceinline__ u32 pack_bf16x2(float a, float b) {   // lo=a, hi=b
    u32 r; asm("cvt.rn.bf16x2.f32 %0, %1, %2;" : "=r"(r) : "f"(b), "f"(a));
    return r;
}
__device__ __forceinline__ u32 pack_f16x2(float a, float b) {    // lo=a, hi=b
    u32 r; asm("cvt.rn.f16x2.f32 %0, %1, %2;" : "=r"(r) : "f"(b), "f"(a));
    return r;
}
__device__ __forceinline__ float ex2f(float x) {
    float y; asm("ex2.approx.f32 %0, %1;" : "=f"(y) : "f"(x)); return y;
}
__device__ __forceinline__ float bf_lo(u32 w) { return __uint_as_float(w << 16); }
__device__ __forceinline__ float bf_hi(u32 w) { return __uint_as_float(w & 0xffff0000u); }
__device__ __forceinline__ void split_pair(float a, float b, u32& hw, u32& lw) {
    hw = pack_bf16x2(a, b);
    lw = pack_bf16x2(a - bf_lo(hw), b - bf_hi(hw));
}
__device__ __forceinline__ void mma_bf(float c[4], const u32 a[4], u32 b0, u32 b1) {
    asm volatile(
        "mma.sync.aligned.m16n8k16.row.col.f32.bf16.bf16.f32 "
        "{%0,%1,%2,%3}, {%4,%5,%6,%7}, {%8,%9}, {%0,%1,%2,%3};"
        : "+f"(c[0]), "+f"(c[1]), "+f"(c[2]), "+f"(c[3])
        : "r"(a[0]), "r"(a[1]), "r"(a[2]), "r"(a[3]), "r"(b0), "r"(b1));
}
__device__ __forceinline__ void mma_fp(float c[4], const u32 a[4], u32 b0, u32 b1) {
    asm volatile(
        "mma.sync.aligned.m16n8k16.row.col.f32.f16.f16.f32 "
        "{%0,%1,%2,%3}, {%4,%5,%6,%7}, {%8,%9}, {%0,%1,%2,%3};"
        : "+f"(c[0]), "+f"(c[1]), "+f"(c[2]), "+f"(c[3])
        : "r"(a[0]), "r"(a[1]), "r"(a[2]), "r"(a[3]), "r"(b0), "r"(b1));
}
__device__ __forceinline__ void ldsm4(u32 r[4], u32 addr) {
    asm volatile("ldmatrix.sync.aligned.m8n8.x4.shared.b16 {%0,%1,%2,%3}, [%4];"
        : "=r"(r[0]), "=r"(r[1]), "=r"(r[2]), "=r"(r[3]) : "r"(addr));
}
__device__ __forceinline__ void ldsm4t(u32 r[4], u32 addr) {
    asm volatile("ldmatrix.sync.aligned.m8n8.x4.trans.shared.b16 {%0,%1,%2,%3}, [%4];"
        : "=r"(r[0]), "=r"(r[1]), "=r"(r[2]), "=r"(r[3]) : "r"(addr));
}

#define PKA 40
#define PNB 136

// ---------------------------------------------------------------------------
// Pre-convert: w_qkv -> fp16 (q rows scaled by QSCALE*LOG2E); x -> fp16
// ---------------------------------------------------------------------------
__global__ __launch_bounds__(256) void conv_w(const float* __restrict__ w)
{
    int i4 = blockIdx.x * 256 + threadIdx.x;          // 196608 total
    float4 v = ((const float4*)w)[i4];
    float sc = (i4 < (HID * CDIM / 4)) ? (QSCALE * LOG2E) : 1.0f;
    ((uint2*)g_w16)[i4] = make_uint2(pack_f16x2(v.x * sc, v.y * sc),
                                     pack_f16x2(v.z * sc, v.w * sc));
}
__global__ __launch_bounds__(256) void conv_x(const float* __restrict__ x)
{
    size_t i4 = (size_t)blockIdx.x * 256 + threadIdx.x;  // 1048576 total
    float4 v = ((const float4*)x)[i4];
    ((uint2*)g_x16)[i4] = make_uint2(pack_f16x2(v.x, v.y), pack_f16x2(v.z, v.w));
}

// ---------------------------------------------------------------------------
// qkv GEMM: fp16 operands, register-prefetch double buffering (flash-proven),
// fused epilogue: q/k -> smem transpose -> [b][h][l][d]; v -> direct [b][h][d][l].
// CTA 128(features) x 128(l), TK=32, 8 warps (4m x 2n).
// ---------------------------------------------------------------------------
#define QKV_SM 34816

__global__ void __launch_bounds__(256, 2) gemm_qkv(void)
{
    __shared__ __align__(16) char smraw[QKV_SM];
    uint16_t* Ah = (uint16_t*)smraw;
    uint16_t* Bh = (uint16_t*)(smraw + 128 * PKA * 2);

    const int tid = threadIdx.x;
    const int lane = tid & 31, wid = tid >> 5;
    const int lam = lane & 3, g = lane >> 2;
    const int wm = (wid & 3) * 32, wn = (wid >> 2) * 64;
    const int m0 = blockIdx.y * 128, n0 = blockIdx.x * 128;
    const int bb = blockIdx.z;

    const uint16_t* Aw = g_w16;
    const uint16_t* Bx = g_x16 + (size_t)bb * CDIM * LSEQ;

    const int ar = tid >> 1, akb = (tid & 1) * 16;
    const int br = tid >> 3, bnb = (tid & 7) * 16;
    const int fr = lane & 15, fc = (lane >> 4) * 8;

    // register prefetch of one k-slice (fp16: 4 x uint4)
    uint4 pa0, pa1, pb0, pb1;
    auto loadAB = [&](int k0) {
        const uint16_t* Ag = Aw + (size_t)(m0 + ar) * CDIM + k0 + akb;
        pa0 = *(const uint4*)(Ag);
        pa1 = *(const uint4*)(Ag + 8);
        const uint16_t* Bg = Bx + (size_t)(k0 + br) * LSEQ + n0 + bnb;
        pb0 = *(const uint4*)(Bg);
        pb1 = *(const uint4*)(Bg + 8);
    };

    float acc[2][8][4];
#pragma unroll
    for (int mt = 0; mt < 2; mt++)
#pragma unroll
        for (int nt = 0; nt < 8; nt++)
#pragma unroll
            for (int r = 0; r < 4; r++) acc[mt][nt][r] = 0.f;

    loadAB(0);

    for (int s = 0; s < 16; s++) {
        __syncthreads();   // prior slice's ldsm reads complete
        *(uint4*)&Ah[ar * PKA + akb]     = pa0;
        *(uint4*)&Ah[ar * PKA + akb + 8] = pa1;
        *(uint4*)&Bh[br * PNB + bnb]     = pb0;
        *(uint4*)&Bh[br * PNB + bnb + 8] = pb1;
        __syncthreads();
        if (s < 15) loadAB((s + 1) * 32);   // LDGs overlap MMA phase

#pragma unroll
        for (int ks = 0; ks < 2; ks++) {
            u32 ahf[2][4];
#pragma unroll
            for (int mt = 0; mt < 2; mt++) {
                u32 off = (u32)((wm + mt * 16 + fr) * PKA + ks * 16 + fc) * 2;
                ldsm4(ahf[mt], smem_u32(Ah) + off);
            }
#pragma unroll
            for (int ntp = 0; ntp < 4; ntp++) {
                u32 bhf[4];
                u32 off = (u32)((ks * 16 + fr) * PNB + wn + ntp * 16 + fc) * 2;
                ldsm4t(bhf, smem_u32(Bh) + off);
#pragma unroll
                for (int mt = 0; mt < 2; mt++) {
                    mma_fp(acc[mt][2 * ntp],     ahf[mt], bhf[0], bhf[1]);
                    mma_fp(acc[mt][2 * ntp + 1], ahf[mt], bhf[2], bhf[3]);
                }
            }
        }
    }
    __syncthreads();

    if (m0 < 1024) {
        // ---- q/k tile: fp16 transpose via smem, then [b][h][l][d] rows
        uint16_t* Ts = (uint16_t*)smraw;             // [n 128][m 128] pitch 136
#pragma unroll
        for (int mt = 0; mt < 2; mt++)
#pragma unroll
            for (int r = 0; r < 2; r++) {
                int ml = wm + mt * 16 + g + r * 8;
#pragma unroll
                for (int nt = 0; nt < 8; nt++) {
                    int nl = wn + nt * 8 + lam * 2;
                    u32 w = pack_f16x2(acc[mt][nt][r * 2], acc[mt][nt][r * 2 + 1]);
                    Ts[nl * 136 + ml]       = (uint16_t)(w & 0xffffu);
                    Ts[(nl + 1) * 136 + ml] = (uint16_t)(w >> 16);
                }
            }
        __syncthreads();
        uint16_t* dstq = (m0 < 512) ? g_qh : g_kh;
        const int ob = m0 & 511;
#pragma unroll
        for (int it = tid; it < 2048; it += 256) {
            int nl = it >> 4, mc = (it & 15) * 8;
            int o = ob + mc;
            int h = o >> 6, d = o & 63;
            uint4 v = *(uint4*)&Ts[nl * 136 + mc];
            *(uint4*)(dstq + (((size_t)(bb * 8 + h) * LSEQ) + n0 + nl) * 64 + d) = v;
        }
    } else {
        // ---- v tile: direct fp16 [b][h][d][l]
        const int o0 = m0 - 1024;
#pragma unroll
        for (int mt = 0; mt < 2; mt++)
#pragma unroll
            for (int r = 0; r < 2; r++) {
                int o = o0 + wm + mt * 16 + g + r * 8;
                int h = o >> 6, d = o & 63;
                uint16_t* dv = g_vh + ((size_t)(bb * 8 + h) * 64 + d) * LSEQ + n0 + wn;
#pragma unroll
                for (int nt = 0; nt < 8; nt++)
                    *(u32*)(dv + nt * 8 + lam * 2) =
                        pack_f16x2(acc[mt][nt][r * 2], acc[mt][nt][r * 2 + 1]);
            }
    }
}

// ---------------------------------------------------------------------------
// bf16-split GEMM (3-term, fp32-grade) for the output projection. (proven)
// ---------------------------------------------------------------------------
__global__ void __launch_bounds__(256, 2) gemm_bf(
    const float* __restrict__ A, const float* __restrict__ Bm,
    float* __restrict__ C, const float* __restrict__ bias,
    int M, int N, int K, long strideB, long strideC)
{
    __shared__ uint16_t Ah[128 * PKA], Al[128 * PKA];
    __shared__ uint16_t Bh[32 * PNB],  Bl[32 * PNB];

    const int tid = threadIdx.x;
    const int lane = tid & 31, wid = tid >> 5;
    const int lam = lane & 3;
    const int wm = (wid & 3) * 32, wn = (wid >> 2) * 64;
    const int m0 = blockIdx.y * 128, n0 = blockIdx.x * 128;
    const float* Bb = Bm + (size_t)blockIdx.z * strideB;
    float* Cb = C + (size_t)blockIdx.z * strideC;

    const int ar = tid >> 1, akb = (tid & 1) * 16;
    const int br = tid >> 3, bnb = (tid & 7) * 16;
    const int fr = lane & 15, fc = (lane >> 4) * 8;

    float acc[2][8][4];
#pragma unroll
    for (int mt = 0; mt < 2; mt++)
#pragma unroll
        for (int nt = 0; nt < 8; nt++)
#pragma unroll
            for (int r = 0; r < 4; r++) acc[mt][nt][r] = 0.f;

    for (int k0 = 0; k0 < K; k0 += 32) {
        const float* Ag = A + (size_t)(m0 + ar) * K + k0 + akb;
#pragma unroll
        for (int q = 0; q < 4; q++) {
            float4 v = *(const float4*)(Ag + q * 4);
            u32 h0, l0, h1, l1;
            split_pair(v.x, v.y, h0, l0);
            split_pair(v.z, v.w, h1, l1);
            int kk = akb + q * 4;
            *(u32*)&Ah[ar * PKA + kk]     = h0;
            *(u32*)&Ah[ar * PKA + kk + 2] = h1;
            *(u32*)&Al[ar * PKA + kk]     = l0;
            *(u32*)&Al[ar * PKA + kk + 2] = l1;
        }
        const float* Bg = Bb + (size_t)(k0 + br) * N + n0 + bnb;
#pragma unroll
        for (int q = 0; q < 4; q++) {
            float4 v = *(const float4*)(Bg + q * 4);
            u32 h0, l0, h1, l1;
            split_pair(v.x, v.y, h0, l0);
            split_pair(v.z, v.w, h1, l1);
            int nn = bnb + q * 4;
            *(u32*)&Bh[br * PNB + nn]     = h0;
            *(u32*)&Bh[br * PNB + nn + 2] = h1;
            *(u32*)&Bl[br * PNB + nn]     = l0;
            *(u32*)&Bl[br * PNB + nn + 2] = l1;
        }
        __syncthreads();

#pragma unroll
        for (int ks = 0; ks < 2; ks++) {
            u32 ahf[2][4], alf[2][4];
#pragma unroll
            for (int mt = 0; mt < 2; mt++) {
                u32 off = (u32)((wm + mt * 16 + fr) * PKA + ks * 16 + fc) * 2;
                ldsm4(ahf[mt], smem_u32(Ah) + off);
                ldsm4(alf[mt], smem_u32(Al) + off);
            }
#pragma unroll
            for (int ntp = 0; ntp < 4; ntp++) {
                u32 bhf[4], blf[4];
                u32 off = (u32)((ks * 16 + fr) * PNB + wn + ntp * 16 + fc) * 2;
                ldsm4t(bhf, smem_u32(Bh) + off);
                ldsm4t(blf, smem_u32(Bl) + off);
#pragma unroll
                for (int mt = 0; mt < 2; mt++) {
                    mma_bf(acc[mt][2 * ntp],     ahf[mt], bhf[0], bhf[1]);
                    mma_bf(acc[mt][2 * ntp + 1], ahf[mt], bhf[2], bhf[3]);
                    mma_bf(acc[mt][2 * ntp],     ahf[mt], blf[0], blf[1]);
                    mma_bf(acc[mt][2 * ntp + 1], ahf[mt], blf[2], blf[3]);
                    mma_bf(acc[mt][2 * ntp],     alf[mt], bhf[0], bhf[1]);
                    mma_bf(acc[mt][2 * ntp + 1], alf[mt], bhf[2], bhf[3]);
                }
            }
        }
        __syncthreads();
    }

    const int g = lane >> 2;
#pragma unroll
    for (int mt = 0; mt < 2; mt++) {
#pragma unroll
        for (int r = 0; r < 2; r++) {
            int m = m0 + wm + mt * 16 + g + r * 8;
            float bv = bias ? bias[m] : 0.0f;
            float* Crow = Cb + (size_t)m * N + n0 + wn;
#pragma unroll
            for (int nt = 0; nt < 8; nt++) {
                float2 o;
                o.x = acc[mt][nt][r * 2 + 0] + bv;
                o.y = acc[mt][nt][r * 2 + 1] + bv;
                *(float2*)(Crow + nt * 8 + lam * 2) = o;
            }
        }
    }
}

// ---------------------------------------------------------------------------
// Flash attention (R15 proven): fp16 single-term, 64-key chunks, 2 CTAs/SM,
// ex2 softmax, K/V register prefetch, scalar FADD row sums.
// ---------------------------------------------------------------------------
#define PD  72
#define POT 132

#define F_QH 0
#define F_KH (128 * PD * 2)
#define F_V  (F_KH + 64 * PD * 2)
#define FLASH_SMEM (F_V + 64 * PD * 2)   // 36864 B

__global__ void __launch_bounds__(256, 2) flash_mma(float* __restrict__ att)
{
    extern __shared__ char smc[];
    uint16_t* Qh = (uint16_t*)(smc + F_QH);
    uint16_t* Kh = (uint16_t*)(smc + F_KH);
    uint16_t* Vs = (uint16_t*)(smc + F_V);

    const int tid = threadIdx.x;
    const int lane = tid & 31, wid = tid >> 5;
    const int g = lane >> 2, lam = lane & 3;
    const int fr = lane & 15, fc = (lane >> 4) * 8;
    const int bh = blockIdx.y;
    const int q0 = blockIdx.x * 128;

    const uint16_t* kh = g_kh + (size_t)bh * LSEQ * DHEAD;
    const uint16_t* vh = g_vh + (size_t)bh * DHEAD * LSEQ;

    const int sr = tid >> 3, sc_ = (tid & 7) * 8;

    uint4 kr0, kr1, vr0, vr1;
    auto loadKV = [&](int n0) {
        kr0 = *(const uint4*)(kh + (size_t)(n0 + sr) * 64 + sc_);
        kr1 = *(const uint4*)(kh + (size_t)(n0 + sr + 32) * 64 + sc_);
        vr0 = *(const uint4*)(vh + (size_t)sr * LSEQ + n0 + sc_);
        vr1 = *(const uint4*)(vh + (size_t)(sr + 32) * LSEQ + n0 + sc_);
    };

    loadKV(0);

    {
        const uint16_t* qh = g_qh + ((size_t)bh * LSEQ + q0) * DHEAD;
#pragma unroll
        for (int it = tid; it < 1024; it += 256) {
            int r = it >> 3, c = (it & 7) * 8;
            *(uint4*)&Qh[r * PD + c] = *(const uint4*)(qh + (size_t)r * 64 + c);
        }
    }

    float o[8][4];
#pragma unroll
    for (int nt = 0; nt < 8; nt++)
#pragma unroll
        for (int r = 0; r < 4; r++) o[nt][r] = 0.f;
    float rs0 = 0.f, rs1 = 0.f;

    const u32 qB = smem_u32(Qh), kB = smem_u32(Kh), vB = smem_u32(Vs);

    for (int n0 = 0; n0 < LSEQ; n0 += 64) {
        __syncthreads();
        *(uint4*)&Kh[sr * PD + sc_]        = kr0;
        *(uint4*)&Kh[(sr + 32) * PD + sc_] = kr1;
        *(uint4*)&Vs[sr * PD + sc_]        = vr0;
        *(uint4*)&Vs[(sr + 32) * PD + sc_] = vr1;
        __syncthreads();
        if (n0 + 64 < LSEQ) loadKV(n0 + 64);

        float s[8][4];
#pragma unroll
        for (int nt = 0; nt < 8; nt++)
#pragma unroll
            for (int r = 0; r < 4; r++) s[nt][r] = 0.f;

#pragma unroll
        for (int ks = 0; ks < 4; ks++) {
            u32 qf[4];
            u32 qoff = (u32)((wid * 16 + fr) * PD + ks * 16 + fc) * 2;
            ldsm4(qf, qB + qoff);
#pragma unroll
            for (int ntp = 0; ntp < 4; ntp++) {
                u32 kf[4];
                u32 koff = (u32)((ntp * 16 + fr) * PD + ks * 16 + fc) * 2;
                ldsm4(kf, kB + koff);
                mma_fp(s[2 * ntp],     qf, kf[0], kf[2]);
                mma_fp(s[2 * ntp + 1], qf, kf[1], kf[3]);
            }
        }

#pragma unroll
        for (int nt = 0; nt < 8; nt++) {
            s[nt][0] = ex2f(s[nt][0]);
            s[nt][1] = ex2f(s[nt][1]);
            s[nt][2] = ex2f(s[nt][2]);
            s[nt][3] = ex2f(s[nt][3]);
            rs0 += s[nt][0] + s[nt][1];
            rs1 += s[nt][2] + s[nt][3];
        }

#pragma unroll
        for (int ks2 = 0; ks2 < 4; ks2++) {
            int t = ks2 * 2;
            u32 pa[4];
            pa[0] = pack_f16x2(s[t][0],     s[t][1]);
            pa[1] = pack_f16x2(s[t][2],     s[t][3]);
            pa[2] = pack_f16x2(s[t + 1][0], s[t + 1][1]);
            pa[3] = pack_f16x2(s[t + 1][2], s[t + 1][3]);
#pragma unroll
            for (int dp = 0; dp < 4; dp++) {
                u32 vf[4];
                u32 voff = (u32)((dp * 16 + fr) * PD + ks2 * 16 + fc) * 2;
                ldsm4(vf, vB + voff);
                mma_fp(o[2 * dp],     pa, vf[0], vf[2]);
                mma_fp(o[2 * dp + 1], pa, vf[1], vf[3]);
            }
        }
    }

    rs0 += __shfl_xor_sync(0xffffffffu, rs0, 1);
    rs0 += __shfl_xor_sync(0xffffffffu, rs0, 2);
    rs1 += __shfl_xor_sync(0xffffffffu, rs1, 1);
    rs1 += __shfl_xor_sync(0xffffffffu, rs1, 2);
    const float inv0 = 1.0f / rs0, inv1 = 1.0f / rs1;

    float* Ot = (float*)smc;
    __syncthreads();
#pragma unroll
    for (int nt = 0; nt < 8; nt++) {
        int d = nt * 8 + 2 * lam;
        int q = wid * 16 + g;
        Ot[d * POT + q]           = o[nt][0] * inv0;
        Ot[(d + 1) * POT + q]     = o[nt][1] * inv0;
        Ot[d * POT + q + 8]       = o[nt][2] * inv1;
        Ot[(d + 1) * POT + q + 8] = o[nt][3] * inv1;
    }
    __syncthreads();
    const int b = bh >> 3, h = bh & 7;
    float* dst = att + ((size_t)b * HID + h * DHEAD) * LSEQ + q0;
#pragma unroll
    for (int it = tid; it < 2048; it += 256) {
        int d = it >> 5, c = (it & 31) * 4;
        *(float4*)(dst + (size_t)d * LSEQ + c) = *(float4*)&Ot[d * POT + c];
    }
}

// ---------------------------------------------------------------------------
extern "C" void kernel_launch(void* const* d_in, const int* in_sizes, int n_in,
                              void* d_out, int out_size)
{
    const float* x     = (const float*)d_in[0];
    const float* w_qkv = (const float*)d_in[1];
    const float* w_out = (const float*)d_in[2];
    const float* b_out = (const float*)d_in[3];
    float* out = (float*)d_out;

    float* att;
    cudaGetSymbolAddress((void**)&att, g_att);

    cudaFuncSetAttribute(flash_mma,
        cudaFuncAttributeMaxDynamicSharedMemorySize, FLASH_SMEM);

    dim3 t(256);
    // 0) fp16 pre-conversion (QSCALE*log2e folded into w_qkv q rows)
    conv_w<<<(O3 * CDIM / 4) / 256, t>>>(w_qkv);
    conv_x<<<(int)(((size_t)B_ * CDIM * LSEQ / 4) / 256), t>>>(x);

    // 1) qkv projection (fp16, register-prefetch pipelined) + fused epilogue
    gemm_qkv<<<dim3(LSEQ / 128, O3 / 128, B_), t>>>();

    // 2) flash attention (fp16, ex2 softmax, K/V reg prefetch, 2 CTAs/SM)
    flash_mma<<<dim3(LSEQ / 128, B_ * HEADS_), t, FLASH_SMEM>>>(att);

    // 3) out = w_out @ att + b_out  (3-term bf16, fp32-grade)
    gemm_bf<<<dim3(LSEQ / 128, CDIM / 128, B_), t>>>(
        w_out, att, out, b_out, CDIM, LSEQ, HID,
        (long)HID * LSEQ, (long)CDIM * LSEQ);
}

// round 17
// speedup vs baseline: 1.5603x; 1.0012x over previous
#include <cuda_runtime.h>
#include <stdint.h>

#define B_     4
#define CDIM   512
#define LSEQ   2048
#define HEADS_ 8
#define DHEAD  64
#define HID    512
#define O3     1536
#define QSCALE 0.125f
#define LOG2E  1.44269504088896f

typedef uint32_t u32;

// ------------------------- scratch (device globals) -------------------------
__device__ uint16_t g_w16[O3 * CDIM];                 // w_qkv fp16 (q rows pre-scaled)
__device__ uint16_t g_x16[(size_t)B_ * CDIM * LSEQ];  // x fp16
__device__ uint16_t g_woh[CDIM * HID], g_wol[CDIM * HID]; // w_out bf16 hi/lo
__device__ uint16_t g_qh[(size_t)B_ * HEADS_ * LSEQ * DHEAD]; // [b][h][l][d] fp16
__device__ uint16_t g_kh[(size_t)B_ * HEADS_ * LSEQ * DHEAD]; // fp16
__device__ uint16_t g_vh[(size_t)B_ * HEADS_ * DHEAD * LSEQ]; // [b][h][d][l] fp16
__device__ uint16_t g_ath[(size_t)B_ * HID * LSEQ];   // att bf16 hi
__device__ uint16_t g_atl[(size_t)B_ * HID * LSEQ];   // att bf16 lo

// ------------------------------- helpers -------------------------------------
__device__ __forceinline__ u32 smem_u32(const void* p) {
    u32 a; asm("{ .reg .u64 t; cvta.to.shared.u64 t, %1; cvt.u32.u64 %0, t; }"
               : "=r"(a) : "l"(p));
    return a;
}
__device__ __forceinline__ u32 pack_bf16x2(float a, float b) {   // lo=a, hi=b
    u32 r; asm("cvt.rn.bf16x2.f32 %0, %1, %2;" : "=r"(r) : "f"(b), "f"(a));
    return r;
}
__device__ __forceinline__ u32 pack_f16x2(float a, float b) {    // lo=a, hi=b
    u32 r; asm("cvt.rn.f16x2.f32 %0, %1, %2;" : "=r"(r) : "f"(b), "f"(a));
    return r;
}
__device__ __forceinline__ float ex2f(float x) {
    float y; asm("ex2.approx.f32 %0, %1;" : "=f"(y) : "f"(x)); return y;
}
__device__ __forceinline__ float bf_lo(u32 w) { return __uint_as_float(w << 16); }
__device__ __forceinline__ float bf_hi(u32 w) { return __uint_as_float(w & 0xffff0000u); }
__device__ __forceinline__ void split_pair(float a, float b, u32& hw, u32& lw) {
    hw = pack_bf16x2(a, b);
    lw = pack_bf16x2(a - bf_lo(hw), b - bf_hi(hw));
}
__device__ __forceinline__ void mma_bf(float c[4], const u32 a[4], u32 b0, u32 b1) {
    asm volatile(
        "mma.sync.aligned.m16n8k16.row.col.f32.bf16.bf16.f32 "
        "{%0,%1,%2,%3}, {%4,%5,%6,%7}, {%8,%9}, {%0,%1,%2,%3};"
        : "+f"(c[0]), "+f"(c[1]), "+f"(c[2]), "+f"(c[3])
        : "r"(a[0]), "r"(a[1]), "r"(a[2]), "r"(a[3]), "r"(b0), "r"(b1));
}
__device__ __forceinline__ void mma_fp(float c[4], const u32 a[4], u32 b0, u32 b1) {
    asm volatile(
        "mma.sync.aligned.m16n8k16.row.col.f32.f16.f16.f32 "
        "{%0,%1,%2,%3}, {%4,%5,%6,%7}, {%8,%9}, {%0,%1,%2,%3};"
        : "+f"(c[0]), "+f"(c[1]), "+f"(c[2]), "+f"(c[3])
        : "r"(a[0]), "r"(a[1]), "r"(a[2]), "r"(a[3]), "r"(b0), "r"(b1));
}
__device__ __forceinline__ void ldsm4(u32 r[4], u32 addr) {
    asm volatile("ldmatrix.sync.aligned.m8n8.x4.shared.b16 {%0,%1,%2,%3}, [%4];"
        : "=r"(r[0]), "=r"(r[1]), "=r"(r[2]), "=r"(r[3]) : "r"(addr));
}
__device__ __forceinline__ void ldsm4t(u32 r[4], u32 addr) {
    asm volatile("ldmatrix.sync.aligned.m8n8.x4.trans.shared.b16 {%0,%1,%2,%3}, [%4];"
        : "=r"(r[0]), "=r"(r[1]), "=r"(r[2]), "=r"(r[3]) : "r"(addr));
}

#define PKA 40
#define PNB 136

// ---------------------------------------------------------------------------
// Pre-converts: w_qkv -> fp16 (q rows scaled), x -> fp16, w_out -> bf16 hi/lo
// ---------------------------------------------------------------------------
__global__ __launch_bounds__(256) void conv_w(const float* __restrict__ w)
{
    int i4 = blockIdx.x * 256 + threadIdx.x;          // 196608 total
    float4 v = ((const float4*)w)[i4];
    float sc = (i4 < (HID * CDIM / 4)) ? (QSCALE * LOG2E) : 1.0f;
    ((uint2*)g_w16)[i4] = make_uint2(pack_f16x2(v.x * sc, v.y * sc),
                                     pack_f16x2(v.z * sc, v.w * sc));
}
__global__ __launch_bounds__(256) void conv_x(const float* __restrict__ x)
{
    size_t i4 = (size_t)blockIdx.x * 256 + threadIdx.x;  // 1048576 total
    float4 v = ((const float4*)x)[i4];
    ((uint2*)g_x16)[i4] = make_uint2(pack_f16x2(v.x, v.y), pack_f16x2(v.z, v.w));
}
__global__ __launch_bounds__(256) void conv_wo(const float* __restrict__ w)
{
    int i4 = blockIdx.x * 256 + threadIdx.x;          // 65536 total
    float4 v = ((const float4*)w)[i4];
    u32 h0, l0, h1, l1;
    split_pair(v.x, v.y, h0, l0);
    split_pair(v.z, v.w, h1, l1);
    ((uint2*)g_woh)[i4] = make_uint2(h0, h1);
    ((uint2*)g_wol)[i4] = make_uint2(l0, l1);
}

// ---------------------------------------------------------------------------
// qkv GEMM (R16 proven): fp16 operands, register-prefetch double buffering,
// fused epilogue: q/k -> smem transpose -> [b][h][l][d]; v -> [b][h][d][l].
// ---------------------------------------------------------------------------
#define QKV_SM 34816

__global__ void __launch_bounds__(256, 2) gemm_qkv(void)
{
    __shared__ __align__(16) char smraw[QKV_SM];
    uint16_t* Ah = (uint16_t*)smraw;
    uint16_t* Bh = (uint16_t*)(smraw + 128 * PKA * 2);

    const int tid = threadIdx.x;
    const int lane = tid & 31, wid = tid >> 5;
    const int lam = lane & 3, g = lane >> 2;
    const int wm = (wid & 3) * 32, wn = (wid >> 2) * 64;
    const int m0 = blockIdx.y * 128, n0 = blockIdx.x * 128;
    const int bb = blockIdx.z;

    const uint16_t* Aw = g_w16;
    const uint16_t* Bx = g_x16 + (size_t)bb * CDIM * LSEQ;

    const int ar = tid >> 1, akb = (tid & 1) * 16;
    const int br = tid >> 3, bnb = (tid & 7) * 16;
    const int fr = lane & 15, fc = (lane >> 4) * 8;

    uint4 pa0, pa1, pb0, pb1;
    auto loadAB = [&](int k0) {
        const uint16_t* Ag = Aw + (size_t)(m0 + ar) * CDIM + k0 + akb;
        pa0 = *(const uint4*)(Ag);
        pa1 = *(const uint4*)(Ag + 8);
        const uint16_t* Bg = Bx + (size_t)(k0 + br) * LSEQ + n0 + bnb;
        pb0 = *(const uint4*)(Bg);
        pb1 = *(const uint4*)(Bg + 8);
    };

    float acc[2][8][4];
#pragma unroll
    for (int mt = 0; mt < 2; mt++)
#pragma unroll
        for (int nt = 0; nt < 8; nt++)
#pragma unroll
            for (int r = 0; r < 4; r++) acc[mt][nt][r] = 0.f;

    loadAB(0);

    for (int s = 0; s < 16; s++) {
        __syncthreads();
        *(uint4*)&Ah[ar * PKA + akb]     = pa0;
        *(uint4*)&Ah[ar * PKA + akb + 8] = pa1;
        *(uint4*)&Bh[br * PNB + bnb]     = pb0;
        *(uint4*)&Bh[br * PNB + bnb + 8] = pb1;
        __syncthreads();
        if (s < 15) loadAB((s + 1) * 32);

#pragma unroll
        for (int ks = 0; ks < 2; ks++) {
            u32 ahf[2][4];
#pragma unroll
            for (int mt = 0; mt < 2; mt++) {
                u32 off = (u32)((wm + mt * 16 + fr) * PKA + ks * 16 + fc) * 2;
                ldsm4(ahf[mt], smem_u32(Ah) + off);
            }
#pragma unroll
            for (int ntp = 0; ntp < 4; ntp++) {
                u32 bhf[4];
                u32 off = (u32)((ks * 16 + fr) * PNB + wn + ntp * 16 + fc) * 2;
                ldsm4t(bhf, smem_u32(Bh) + off);
#pragma unroll
                for (int mt = 0; mt < 2; mt++) {
                    mma_fp(acc[mt][2 * ntp],     ahf[mt], bhf[0], bhf[1]);
                    mma_fp(acc[mt][2 * ntp + 1], ahf[mt], bhf[2], bhf[3]);
                }
            }
        }
    }
    __syncthreads();

    if (m0 < 1024) {
        uint16_t* Ts = (uint16_t*)smraw;             // [n 128][m 128] pitch 136
#pragma unroll
        for (int mt = 0; mt < 2; mt++)
#pragma unroll
            for (int r = 0; r < 2; r++) {
                int ml = wm + mt * 16 + g + r * 8;
#pragma unroll
                for (int nt = 0; nt < 8; nt++) {
                    int nl = wn + nt * 8 + lam * 2;
                    u32 w = pack_f16x2(acc[mt][nt][r * 2], acc[mt][nt][r * 2 + 1]);
                    Ts[nl * 136 + ml]       = (uint16_t)(w & 0xffffu);
                    Ts[(nl + 1) * 136 + ml] = (uint16_t)(w >> 16);
                }
            }
        __syncthreads();
        uint16_t* dstq = (m0 < 512) ? g_qh : g_kh;
        const int ob = m0 & 511;
#pragma unroll
        for (int it = tid; it < 2048; it += 256) {
            int nl = it >> 4, mc = (it & 15) * 8;
            int o = ob + mc;
            int h = o >> 6, d = o & 63;
            uint4 v = *(uint4*)&Ts[nl * 136 + mc];
            *(uint4*)(dstq + (((size_t)(bb * 8 + h) * LSEQ) + n0 + nl) * 64 + d) = v;
        }
    } else {
        const int o0 = m0 - 1024;
#pragma unroll
        for (int mt = 0; mt < 2; mt++)
#pragma unroll
            for (int r = 0; r < 2; r++) {
                int o = o0 + wm + mt * 16 + g + r * 8;
                int h = o >> 6, d = o & 63;
                uint16_t* dv = g_vh + ((size_t)(bb * 8 + h) * 64 + d) * LSEQ + n0 + wn;
#pragma unroll
                for (int nt = 0; nt < 8; nt++)
                    *(u32*)(dv + nt * 8 + lam * 2) =
                        pack_f16x2(acc[mt][nt][r * 2], acc[mt][nt][r * 2 + 1]);
            }
    }
}

// ---------------------------------------------------------------------------
// Output GEMM: pre-split bf16 operands (copy staging), B register-prefetch,
// 3-term AhBh + AhBl + AlBh. out = w_out @ att + b_out.
// ---------------------------------------------------------------------------
__global__ void __launch_bounds__(256, 2) gemm_out(
    float* __restrict__ C, const float* __restrict__ bias)
{
    __shared__ uint16_t Ah[128 * PKA], Al[128 * PKA];
    __shared__ uint16_t Bh[32 * PNB],  Bl[32 * PNB];

    const int tid = threadIdx.x;
    const int lane = tid & 31, wid = tid >> 5;
    const int lam = lane & 3;
    const int wm = (wid & 3) * 32, wn = (wid >> 2) * 64;
    const int m0 = blockIdx.y * 128, n0 = blockIdx.x * 128;
    const int bb = blockIdx.z;
    const uint16_t* Bhg = g_ath + (size_t)bb * HID * LSEQ;
    const uint16_t* Blg = g_atl + (size_t)bb * HID * LSEQ;
    float* Cb = C + (size_t)bb * CDIM * LSEQ;

    const int ar = tid >> 1, akb = (tid & 1) * 16;
    const int br = tid >> 3, bnb = (tid & 7) * 16;
    const int fr = lane & 15, fc = (lane >> 4) * 8;

    // B (att) register prefetch: hi+lo, 4 x uint4
    uint4 pb0, pb1, pl0, pl1;
    auto loadB = [&](int k0) {
        const size_t boff = (size_t)(k0 + br) * LSEQ + n0 + bnb;
        pb0 = *(const uint4*)(Bhg + boff);
        pb1 = *(const uint4*)(Bhg + boff + 8);
        pl0 = *(const uint4*)(Blg + boff);
        pl1 = *(const uint4*)(Blg + boff + 8);
    };

    float acc[2][8][4];
#pragma unroll
    for (int mt = 0; mt < 2; mt++)
#pragma unroll
        for (int nt = 0; nt < 8; nt++)
#pragma unroll
            for (int r = 0; r < 4; r++) acc[mt][nt][r] = 0.f;

    loadB(0);

    for (int s = 0; s < 16; s++) {
        const int k0 = s * 32;
        __syncthreads();
        // A (weights, L2-resident): plain fp16 copy staging
        {
            const size_t aoff = (size_t)(m0 + ar) * HID + k0 + akb;
            *(uint4*)&Ah[ar * PKA + akb]     = *(const uint4*)(g_woh + aoff);
            *(uint4*)&Ah[ar * PKA + akb + 8] = *(const uint4*)(g_woh + aoff + 8);
            *(uint4*)&Al[ar * PKA + akb]     = *(const uint4*)(g_wol + aoff);
            *(uint4*)&Al[ar * PKA + akb + 8] = *(const uint4*)(g_wol + aoff + 8);
        }
        *(uint4*)&Bh[br * PNB + bnb]     = pb0;
        *(uint4*)&Bh[br * PNB + bnb + 8] = pb1;
        *(uint4*)&Bl[br * PNB + bnb]     = pl0;
        *(uint4*)&Bl[br * PNB + bnb + 8] = pl1;
        __syncthreads();
        if (s < 15) loadB(k0 + 32);

#pragma unroll
        for (int ks = 0; ks < 2; ks++) {
            u32 ahf[2][4], alf[2][4];
#pragma unroll
            for (int mt = 0; mt < 2; mt++) {
                u32 off = (u32)((wm + mt * 16 + fr) * PKA + ks * 16 + fc) * 2;
                ldsm4(ahf[mt], smem_u32(Ah) + off);
                ldsm4(alf[mt], smem_u32(Al) + off);
            }
#pragma unroll
            for (int ntp = 0; ntp < 4; ntp++) {
                u32 bhf[4], blf[4];
                u32 off = (u32)((ks * 16 + fr) * PNB + wn + ntp * 16 + fc) * 2;
                ldsm4t(bhf, smem_u32(Bh) + off);
                ldsm4t(blf, smem_u32(Bl) + off);
#pragma unroll
                for (int mt = 0; mt < 2; mt++) {
                    mma_bf(acc[mt][2 * ntp],     ahf[mt], bhf[0], bhf[1]);
                    mma_bf(acc[mt][2 * ntp + 1], ahf[mt], bhf[2], bhf[3]);
                    mma_bf(acc[mt][2 * ntp],     ahf[mt], blf[0], blf[1]);
                    mma_bf(acc[mt][2 * ntp + 1], ahf[mt], blf[2], blf[3]);
                    mma_bf(acc[mt][2 * ntp],     alf[mt], bhf[0], bhf[1]);
                    mma_bf(acc[mt][2 * ntp + 1], alf[mt], bhf[2], bhf[3]);
                }
            }
        }
    }

    const int g = lane >> 2;
#pragma unroll
    for (int mt = 0; mt < 2; mt++) {
#pragma unroll
        for (int r = 0; r < 2; r++) {
            int m = m0 + wm + mt * 16 + g + r * 8;
            float bv = bias[m];
            float* Crow = Cb + (size_t)m * LSEQ + n0 + wn;
#pragma unroll
            for (int nt = 0; nt < 8; nt++) {
                float2 o;
                o.x = acc[mt][nt][r * 2 + 0] + bv;
                o.y = acc[mt][nt][r * 2 + 1] + bv;
                *(float2*)(Crow + nt * 8 + lam * 2) = o;
            }
        }
    }
}

// ---------------------------------------------------------------------------
// Flash attention: fp16 single-term, 64-key chunks, K/V register prefetch,
// ping-pong K/V smem (ONE barrier per chunk), ex2 softmax, 2 CTAs/SM.
// Emits att as bf16 hi/lo.
// ---------------------------------------------------------------------------
#define PD  72
#define POT 132

#define F_Q    0
#define F_KV0  (128 * PD * 2)            // 18432
#define KV_STG (64 * PD * 2 * 2)         // K(9216)+V(9216) = 18432
#define FLASH_SMEM (F_KV0 + 2 * KV_STG)  // 55296 B

__global__ void __launch_bounds__(256, 2) flash_mma(void)
{
    extern __shared__ char smc[];
    uint16_t* Qh = (uint16_t*)(smc + F_Q);

    const int tid = threadIdx.x;
    const int lane = tid & 31, wid = tid >> 5;
    const int g = lane >> 2, lam = lane & 3;
    const int fr = lane & 15, fc = (lane >> 4) * 8;
    const int bh = blockIdx.y;
    const int q0 = blockIdx.x * 128;

    const uint16_t* kh = g_kh + (size_t)bh * LSEQ * DHEAD;
    const uint16_t* vh = g_vh + (size_t)bh * DHEAD * LSEQ;

    const int sr = tid >> 3, sc_ = (tid & 7) * 8;

    uint4 kr0, kr1, vr0, vr1;
    auto loadKV = [&](int n0) {
        kr0 = *(const uint4*)(kh + (size_t)(n0 + sr) * 64 + sc_);
        kr1 = *(const uint4*)(kh + (size_t)(n0 + sr + 32) * 64 + sc_);
        vr0 = *(const uint4*)(vh + (size_t)sr * LSEQ + n0 + sc_);
        vr1 = *(const uint4*)(vh + (size_t)(sr + 32) * LSEQ + n0 + sc_);
    };

    loadKV(0);

    {
        const uint16_t* qh = g_qh + ((size_t)bh * LSEQ + q0) * DHEAD;
#pragma unroll
        for (int it = tid; it < 1024; it += 256) {
            int r = it >> 3, c = (it & 7) * 8;
            *(uint4*)&Qh[r * PD + c] = *(const uint4*)(qh + (size_t)r * 64 + c);
        }
    }

    float o[8][4];
#pragma unroll
    for (int nt = 0; nt < 8; nt++)
#pragma unroll
        for (int r = 0; r < 4; r++) o[nt][r] = 0.f;
    float rs0 = 0.f, rs1 = 0.f;

    const u32 qB = smem_u32(Qh);
    const u32 kvBase = smem_u32(smc + F_KV0);

    for (int c = 0; c < 32; c++) {
        const u32 kB = kvBase + (u32)(c & 1) * KV_STG;
        const u32 vB = kB + 64 * PD * 2;
        uint16_t* Kc = (uint16_t*)(smc + F_KV0 + (c & 1) * KV_STG);
        uint16_t* Vc = Kc + 64 * PD;

        // store this chunk (buffer c&1; other buffer still being computed on)
        *(uint4*)&Kc[sr * PD + sc_]        = kr0;
        *(uint4*)&Kc[(sr + 32) * PD + sc_] = kr1;
        *(uint4*)&Vc[sr * PD + sc_]        = vr0;
        *(uint4*)&Vc[(sr + 32) * PD + sc_] = vr1;
        __syncthreads();   // single barrier: staging visible; prev compute done
        if (c < 31) loadKV((c + 1) * 64);

        float s[8][4];
#pragma unroll
        for (int nt = 0; nt < 8; nt++)
#pragma unroll
            for (int r = 0; r < 4; r++) s[nt][r] = 0.f;

#pragma unroll
        for (int ks = 0; ks < 4; ks++) {
            u32 qf[4];
            u32 qoff = (u32)((wid * 16 + fr) * PD + ks * 16 + fc) * 2;
            ldsm4(qf, qB + qoff);
#pragma unroll
            for (int ntp = 0; ntp < 4; ntp++) {
                u32 kf[4];
                u32 koff = (u32)((ntp * 16 + fr) * PD + ks * 16 + fc) * 2;
                ldsm4(kf, kB + koff);
                mma_fp(s[2 * ntp],     qf, kf[0], kf[2]);
                mma_fp(s[2 * ntp + 1], qf, kf[1], kf[3]);
            }
        }

#pragma unroll
        for (int nt = 0; nt < 8; nt++) {
            s[nt][0] = ex2f(s[nt][0]);
            s[nt][1] = ex2f(s[nt][1]);
            s[nt][2] = ex2f(s[nt][2]);
            s[nt][3] = ex2f(s[nt][3]);
            rs0 += s[nt][0] + s[nt][1];
            rs1 += s[nt][2] + s[nt][3];
        }

#pragma unroll
        for (int ks2 = 0; ks2 < 4; ks2++) {
            int t = ks2 * 2;
            u32 pa[4];
            pa[0] = pack_f16x2(s[t][0],     s[t][1]);
            pa[1] = pack_f16x2(s[t][2],     s[t][3]);
            pa[2] = pack_f16x2(s[t + 1][0], s[t + 1][1]);
            pa[3] = pack_f16x2(s[t + 1][2], s[t + 1][3]);
#pragma unroll
            for (int dp = 0; dp < 4; dp++) {
                u32 vf[4];
                u32 voff = (u32)((dp * 16 + fr) * PD + ks2 * 16 + fc) * 2;
                ldsm4(vf, vB + voff);
                mma_fp(o[2 * dp],     pa, vf[0], vf[2]);
                mma_fp(o[2 * dp + 1], pa, vf[1], vf[3]);
            }
        }
    }

    rs0 += __shfl_xor_sync(0xffffffffu, rs0, 1);
    rs0 += __shfl_xor_sync(0xffffffffu, rs0, 2);
    rs1 += __shfl_xor_sync(0xffffffffu, rs1, 1);
    rs1 += __shfl_xor_sync(0xffffffffu, rs1, 2);
    const float inv0 = 1.0f / rs0, inv1 = 1.0f / rs1;

    float* Ot = (float*)smc;   // 64 x POT floats = 33792 B, fits
    __syncthreads();
#pragma unroll
    for (int nt = 0; nt < 8; nt++) {
        int d = nt * 8 + 2 * lam;
        int q = wid * 16 + g;
        Ot[d * POT + q]           = o[nt][0] * inv0;
        Ot[(d + 1) * POT + q]     = o[nt][1] * inv0;
        Ot[d * POT + q + 8]       = o[nt][2] * inv1;
        Ot[(d + 1) * POT + q + 8] = o[nt][3] * inv1;
    }
    __syncthreads();
    const int b = bh >> 3, h = bh & 7;
    const size_t obase = ((size_t)b * HID + h * DHEAD) * LSEQ + q0;
#pragma unroll
    for (int it = tid; it < 2048; it += 256) {
        int d = it >> 5, cc = (it & 31) * 4;
        float4 v = *(float4*)&Ot[d * POT + cc];
        u32 h0, l0, h1, l1;
        split_pair(v.x, v.y, h0, l0);
        split_pair(v.z, v.w, h1, l1);
        size_t off = obase + (size_t)d * LSEQ + cc;
        *(uint2*)(g_ath + off) = make_uint2(h0, h1);
        *(uint2*)(g_atl + off) = make_uint2(l0, l1);
    }
}

// ---------------------------------------------------------------------------
extern "C" void kernel_launch(void* const* d_in, const int* in_sizes, int n_in,
                              void* d_out, int out_size)
{
    const float* x     = (const float*)d_in[0];
    const float* w_qkv = (const float*)d_in[1];
    const float* w_out = (const float*)d_in[2];
    const float* b_out = (const float*)d_in[3];
    float* out = (float*)d_out;

    cudaFuncSetAttribute(flash_mma,
        cudaFuncAttributeMaxDynamicSharedMemorySize, FLASH_SMEM);

    dim3 t(256);
    // 0) pre-conversions
    conv_w<<<(O3 * CDIM / 4) / 256, t>>>(w_qkv);
    conv_x<<<(int)(((size_t)B_ * CDIM * LSEQ / 4) / 256), t>>>(x);
    conv_wo<<<(CDIM * HID / 4) / 256, t>>>(w_out);

    // 1) qkv projection (fp16, register-prefetch) + fused layout epilogue
    gemm_qkv<<<dim3(LSEQ / 128, O3 / 128, B_), t>>>();

    // 2) flash attention (ping-pong K/V, 1 barrier/chunk; bf16 hi/lo att out)
    flash_mma<<<dim3(LSEQ / 128, B_ * HEADS_), t, FLASH_SMEM>>>();

    // 3) out = w_out @ att + b_out (pre-split operands, B prefetch, 3-term)
    gemm_out<<<dim3(LSEQ / 128, CDIM / 128, B_), t>>>(out, b_out);
}